// round 1
// baseline (speedup 1.0000x reference)
#include <cuda_runtime.h>

// MeshUnpool: out[b,f,t] = (1/occ[b,t]) * sum_e features[b,f,e] * group[b,e,t]
// group is a ~0.1%-dense 0/1 mask. Strategy: stream group once (384 MB, the
// HBM-bound term), accumulate sparse hits into a shared-memory tile, scale by
// 1/occ at writeout. Features are pre-transposed to [B,E,NF] so each hit reads
// a contiguous 256B column.

#define BB 4
#define NF 64
#define EE 4000
#define TT 6000

#define TILE_T 64
#define NLANE  (TILE_T / 4)        // 16 float4 lanes
#define NTHREADS 256
#define NSPLIT (NTHREADS / NLANE)  // 16 E-splits
#define EPT    (EE / NSPLIT)       // 250 rows per split
#define NTILES ((TT + TILE_T - 1) / TILE_T)  // 94

// 4 MB scratch for transposed features [B][E][NF] (allocation-free rule:
// __device__ global array).
__device__ __align__(16) float g_featT[BB * EE * NF];

// ---------------------------------------------------------------------------
// Kernel 1: transpose features [B, NF, E] -> featT [B, E, NF]
// Tiled 32x32 shared transpose; NF=64 and E=4000 are both multiples of 32.
// ---------------------------------------------------------------------------
__global__ void transpose_feat_kernel(const float* __restrict__ feat) {
    __shared__ float tile[32][33];
    const int b  = blockIdx.z;
    const int e0 = blockIdx.x * 32;
    const int f0 = blockIdx.y * 32;
    const int tx = threadIdx.x;   // 0..31
    const int ty = threadIdx.y;   // 0..7

#pragma unroll
    for (int j = 0; j < 32; j += 8) {
        // coalesced read along E
        tile[ty + j][tx] = feat[((size_t)(b * NF + f0 + ty + j)) * EE + e0 + tx];
    }
    __syncthreads();
#pragma unroll
    for (int j = 0; j < 32; j += 8) {
        // coalesced write along NF (featT[b][e][f])
        g_featT[((size_t)b * EE + (e0 + ty + j)) * NF + f0 + tx] = tile[tx][ty + j];
    }
}

// ---------------------------------------------------------------------------
// Kernel 2: sparse accumulate + scale
// Block = (b, t-tile of 64). 256 threads = 16 float4 t-lanes x 16 E-splits.
// ---------------------------------------------------------------------------
__device__ __forceinline__ void accum_hit(float g, int b, int e, int tt,
                                          float (*acc)[TILE_T]) {
    const float4* fp =
        reinterpret_cast<const float4*>(g_featT + ((size_t)b * EE + e) * NF);
#pragma unroll
    for (int i = 0; i < NF / 4; i++) {
        float4 f = fp[i];
        atomicAdd(&acc[4 * i + 0][tt], g * f.x);
        atomicAdd(&acc[4 * i + 1][tt], g * f.y);
        atomicAdd(&acc[4 * i + 2][tt], g * f.z);
        atomicAdd(&acc[4 * i + 3][tt], g * f.w);
    }
}

__device__ __forceinline__ void process_vec(float4 v, int b, int e, int tloc,
                                            float (*acc)[TILE_T]) {
    if (v.x != 0.0f) accum_hit(v.x, b, e, tloc + 0, acc);
    if (v.y != 0.0f) accum_hit(v.y, b, e, tloc + 1, acc);
    if (v.z != 0.0f) accum_hit(v.z, b, e, tloc + 2, acc);
    if (v.w != 0.0f) accum_hit(v.w, b, e, tloc + 3, acc);
}

__global__ void __launch_bounds__(NTHREADS, 1)
unpool_kernel(const float* __restrict__ group,
              const float* __restrict__ occ,
              float* __restrict__ out) {
    __shared__ float acc[NF][TILE_T];     // 16 KB
    __shared__ float inv_occ[TILE_T];

    const int b    = blockIdx.x / NTILES;
    const int tile = blockIdx.x % NTILES;
    const int t0   = tile * TILE_T;
    const int tid  = threadIdx.x;

    // zero accumulator
#pragma unroll
    for (int i = tid; i < NF * TILE_T; i += NTHREADS)
        (&acc[0][0])[i] = 0.0f;
    if (tid < TILE_T) {
        int t = t0 + tid;
        inv_occ[tid] = (t < TT) ? (1.0f / occ[(size_t)b * TT + t]) : 0.0f;
    }
    __syncthreads();

    const int lane4  = tid & (NLANE - 1);   // which float4 of the tile
    const int esplit = tid >> 4;            // which E-split
    const int tloc   = lane4 * 4;
    const bool valid = (t0 + tloc) < TT;    // TT % 4 == 0, so float4 granularity safe

    if (valid) {
        const float* gbase = group + (size_t)b * EE * TT + t0 + tloc;
        const int e_begin = esplit * EPT;
        // EPT = 250 = 50 * 5: unroll by 5 for MLP on the streaming loads.
        for (int e = e_begin; e < e_begin + EPT; e += 5) {
            float4 v0 = __ldcs(reinterpret_cast<const float4*>(gbase + (size_t)(e + 0) * TT));
            float4 v1 = __ldcs(reinterpret_cast<const float4*>(gbase + (size_t)(e + 1) * TT));
            float4 v2 = __ldcs(reinterpret_cast<const float4*>(gbase + (size_t)(e + 2) * TT));
            float4 v3 = __ldcs(reinterpret_cast<const float4*>(gbase + (size_t)(e + 3) * TT));
            float4 v4 = __ldcs(reinterpret_cast<const float4*>(gbase + (size_t)(e + 4) * TT));
            process_vec(v0, b, e + 0, tloc, acc);
            process_vec(v1, b, e + 1, tloc, acc);
            process_vec(v2, b, e + 2, tloc, acc);
            process_vec(v3, b, e + 3, tloc, acc);
            process_vec(v4, b, e + 4, tloc, acc);
        }
    }
    __syncthreads();

    // writeout: out[b, f, t0+tt] = acc[f][tt] * inv_occ[tt]
    for (int i = tid; i < NF * TILE_T; i += NTHREADS) {
        int f  = i / TILE_T;
        int tt = i % TILE_T;
        int t  = t0 + tt;
        if (t < TT)
            out[((size_t)b * NF + f) * TT + t] = acc[f][tt] * inv_occ[tt];
    }
}

extern "C" void kernel_launch(void* const* d_in, const int* in_sizes, int n_in,
                              void* d_out, int out_size) {
    const float* features = (const float*)d_in[0];   // [B, NF, E]
    const float* group    = (const float*)d_in[1];   // [B, E, T]
    const float* occ      = (const float*)d_in[2];   // [B, T]
    float* out = (float*)d_out;                      // [B, NF, T]

    dim3 tgrid(EE / 32, NF / 32, BB);
    dim3 tblk(32, 8);
    transpose_feat_kernel<<<tgrid, tblk>>>(features);

    unpool_kernel<<<BB * NTILES, NTHREADS>>>(group, occ, out);
}

// round 2
// speedup vs baseline: 8.8623x; 8.8623x over previous
#include <cuda_runtime.h>

// MeshUnpool: out[b,f,t] = (1/occ[b,t]) * sum_e features[b,f,e] * group[b,e,t]
// group is a ~0.1%-dense 0/1 mask (values exactly 0.0 or 1.0).
//
// R2: two-phase per block. Phase A streams group and records nonzero (e,tt)
// hits in a shared queue (no hot-path atomics). Phase B assigns each warp an
// exclusive set of tt-columns, so accumulation is plain LDS/FADD/STS.
// This removes the R1 bottleneck: 64 same-bank smem ATOMS per hit
// (2048 cyc/hit = the entire 760us).

#define BB 4
#define NF 64
#define EE 4000
#define TT 6000

#define TILE_T 64
#define NLANE  (TILE_T / 4)        // 16 float4 lanes
#define NTHREADS 256
#define NSPLIT (NTHREADS / NLANE)  // 16 E-splits
#define EPT    (EE / NSPLIT)       // 250 rows per split
#define UNROLL 10                  // 25 outer iterations
#define NTILES ((TT + TILE_T - 1) / TILE_T)  // 94
#define HITS_MAX 1024              // expected ~256/block; 1024 is >>16 sigma

// 4 MB scratch for transposed features [B][E][NF].
__device__ __align__(16) float g_featT[BB * EE * NF];

// ---------------------------------------------------------------------------
// Kernel 1: transpose features [B, NF, E] -> featT [B, E, NF]
// ---------------------------------------------------------------------------
__global__ void transpose_feat_kernel(const float* __restrict__ feat) {
    __shared__ float tile[32][33];
    const int b  = blockIdx.z;
    const int e0 = blockIdx.x * 32;
    const int f0 = blockIdx.y * 32;
    const int tx = threadIdx.x;   // 0..31
    const int ty = threadIdx.y;   // 0..7

#pragma unroll
    for (int j = 0; j < 32; j += 8)
        tile[ty + j][tx] = feat[((size_t)(b * NF + f0 + ty + j)) * EE + e0 + tx];
    __syncthreads();
#pragma unroll
    for (int j = 0; j < 32; j += 8)
        g_featT[((size_t)b * EE + (e0 + ty + j)) * NF + f0 + tx] = tile[tx][ty + j];
}

// ---------------------------------------------------------------------------
// Kernel 2: stream + two-phase sparse accumulate
// ---------------------------------------------------------------------------
__global__ void __launch_bounds__(NTHREADS)
unpool_kernel(const float* __restrict__ group,
              const float* __restrict__ occ,
              float* __restrict__ out) {
    __shared__ float acc[TILE_T][NF + 1];   // padded: bank(acc[tt][f]) = (tt+f)%32
    __shared__ float inv_occ[TILE_T];
    __shared__ int   hits[HITS_MAX];        // packed (e << 8) | tt
    __shared__ int   nhits;

    const int b    = blockIdx.x / NTILES;
    const int tile = blockIdx.x % NTILES;
    const int t0   = tile * TILE_T;
    const int tid  = threadIdx.x;

    // init
    for (int i = tid; i < TILE_T * (NF + 1); i += NTHREADS)
        (&acc[0][0])[i] = 0.0f;
    if (tid < TILE_T) {
        int t = t0 + tid;
        inv_occ[tid] = (t < TT) ? (1.0f / occ[(size_t)b * TT + t]) : 0.0f;
    }
    if (tid == 0) nhits = 0;
    __syncthreads();

    // ---- Phase A: stream group, record nonzero coordinates ----
    const int lane4  = tid & (NLANE - 1);   // which float4 inside the t-tile
    const int esplit = tid >> 4;            // which E-split
    const int tloc   = lane4 * 4;
    const bool valid = (t0 + tloc) < TT;    // TT % 4 == 0, float4-granular

    if (valid) {
        const float* gbase = group + (size_t)b * EE * TT + t0 + tloc;
        const int e_begin = esplit * EPT;
        for (int it = 0; it < EPT / UNROLL; it++) {
            const int eb = e_begin + it * UNROLL;
            float4 v[UNROLL];
#pragma unroll
            for (int u = 0; u < UNROLL; u++)
                v[u] = __ldcs(reinterpret_cast<const float4*>(
                    gbase + (size_t)(eb + u) * TT));
#pragma unroll
            for (int u = 0; u < UNROLL; u++) {
                unsigned ored = __float_as_uint(v[u].x) | __float_as_uint(v[u].y) |
                                __float_as_uint(v[u].z) | __float_as_uint(v[u].w);
                if (ored) {  // rare (~1% of warp-iterations per component)
                    const int e = eb + u;
                    const float c[4] = {v[u].x, v[u].y, v[u].z, v[u].w};
#pragma unroll
                    for (int k = 0; k < 4; k++) {
                        if (__float_as_uint(c[k])) {
                            int idx = atomicAdd(&nhits, 1);
                            if (idx < HITS_MAX)
                                hits[idx] = (e << 8) | (tloc + k);
                        }
                    }
                }
            }
        }
    }
    __syncthreads();

    // ---- Phase B: warp w exclusively owns tt in [8w, 8w+8) ----
    {
        const int wid  = tid >> 5;
        const int lane = tid & 31;
        const int n = (nhits < HITS_MAX) ? nhits : HITS_MAX;
        for (int i = 0; i < n; i++) {
            const int h  = hits[i];         // LDS broadcast
            const int tt = h & 0xFF;
            if ((tt >> 3) == wid) {
                const int e = h >> 8;
                const float* col = g_featT + ((size_t)b * EE + e) * NF;
                // group values are exactly 1.0 at hits: accumulate feature col
                acc[tt][lane]      += col[lane];        // banks (tt+lane)%32: free
                acc[tt][lane + 32] += col[lane + 32];
            }
        }
    }
    __syncthreads();

    // ---- writeout: out[b, f, t0+tt] = acc[tt][f] * inv_occ[tt] ----
    for (int i = tid; i < NF * TILE_T; i += NTHREADS) {
        const int f  = i / TILE_T;
        const int tt = i % TILE_T;          // consecutive tid -> consecutive t
        const int t  = t0 + tt;
        if (t < TT)
            out[((size_t)b * NF + f) * TT + t] = acc[tt][f] * inv_occ[tt];
    }
}

extern "C" void kernel_launch(void* const* d_in, const int* in_sizes, int n_in,
                              void* d_out, int out_size) {
    const float* features = (const float*)d_in[0];   // [B, NF, E]
    const float* group    = (const float*)d_in[1];   // [B, E, T]
    const float* occ      = (const float*)d_in[2];   // [B, T]
    float* out = (float*)d_out;                      // [B, NF, T]

    dim3 tgrid(EE / 32, NF / 32, BB);
    dim3 tblk(32, 8);
    transpose_feat_kernel<<<tgrid, tblk>>>(features);

    unpool_kernel<<<BB * NTILES, NTHREADS>>>(group, occ, out);
}

// round 3
// speedup vs baseline: 8.8788x; 1.0019x over previous
#include <cuda_runtime.h>

// MeshUnpool: out[b,f,t] = (1/occ[b,t]) * sum_e features[b,f,e] * group[b,e,t]
// group is a ~0.1%-dense 0/1 mask. Stream group once (384 MB, HBM-bound),
// record sparse hits, accumulate via warp-exclusive tt ownership (no atomics
// on the hot path).
//
// R3: TILE_T 64->32, 128-thread blocks, grid 376->752. Occupancy was
// grid-limited at 31% (2.5 blocks/SM); now 8 blocks/SM (reg-limited) = 50%,
// raising outstanding-load count toward the DRAM latency-BW product.

#define BB 4
#define NF 64
#define EE 4000
#define TT 6000

#define TILE_T 32
#define NLANE  (TILE_T / 4)        // 8 float4 lanes
#define NTHREADS 128
#define NSPLIT (NTHREADS / NLANE)  // 16 E-splits
#define EPT    (EE / NSPLIT)       // 250 rows per split
#define UNROLL 10                  // 25 outer iterations
#define NTILES ((TT + TILE_T - 1) / TILE_T)  // 188
#define HITS_MAX 768               // expected ~128/block

// 4 MB scratch for transposed features [B][E][NF].
__device__ __align__(16) float g_featT[BB * EE * NF];

// ---------------------------------------------------------------------------
// Kernel 1: transpose features [B, NF, E] -> featT [B, E, NF]
// ---------------------------------------------------------------------------
__global__ void transpose_feat_kernel(const float* __restrict__ feat) {
    __shared__ float tile[32][33];
    const int b  = blockIdx.z;
    const int e0 = blockIdx.x * 32;
    const int f0 = blockIdx.y * 32;
    const int tx = threadIdx.x;   // 0..31
    const int ty = threadIdx.y;   // 0..7

#pragma unroll
    for (int j = 0; j < 32; j += 8)
        tile[ty + j][tx] = feat[((size_t)(b * NF + f0 + ty + j)) * EE + e0 + tx];
    __syncthreads();
#pragma unroll
    for (int j = 0; j < 32; j += 8)
        g_featT[((size_t)b * EE + (e0 + ty + j)) * NF + f0 + tx] = tile[tx][ty + j];
}

// ---------------------------------------------------------------------------
// Kernel 2: stream + two-phase sparse accumulate
// ---------------------------------------------------------------------------
__global__ void __launch_bounds__(NTHREADS, 8)
unpool_kernel(const float* __restrict__ group,
              const float* __restrict__ occ,
              float* __restrict__ out) {
    __shared__ float acc[TILE_T][NF + 1];   // bank(acc[tt][f]) = (tt+f)%32
    __shared__ float inv_occ[TILE_T];
    __shared__ int   hits[HITS_MAX];        // packed (e << 8) | tt
    __shared__ int   nhits;

    const int b    = blockIdx.x / NTILES;
    const int tile = blockIdx.x % NTILES;
    const int t0   = tile * TILE_T;
    const int tid  = threadIdx.x;

    // init
    for (int i = tid; i < TILE_T * (NF + 1); i += NTHREADS)
        (&acc[0][0])[i] = 0.0f;
    if (tid < TILE_T) {
        int t = t0 + tid;
        inv_occ[tid] = (t < TT) ? (1.0f / occ[(size_t)b * TT + t]) : 0.0f;
    }
    if (tid == 0) nhits = 0;
    __syncthreads();

    // ---- Phase A: stream group, record nonzero coordinates ----
    const int lane4  = tid & (NLANE - 1);   // which float4 inside the t-tile
    const int esplit = tid / NLANE;         // which E-split
    const int tloc   = lane4 * 4;
    const bool valid = (t0 + tloc) < TT;    // TT % 4 == 0, float4-granular

    if (valid) {
        const float* gbase = group + (size_t)b * EE * TT + t0 + tloc;
        const int e_begin = esplit * EPT;
        for (int it = 0; it < EPT / UNROLL; it++) {
            const int eb = e_begin + it * UNROLL;
            float4 v[UNROLL];
#pragma unroll
            for (int u = 0; u < UNROLL; u++)
                v[u] = __ldcs(reinterpret_cast<const float4*>(
                    gbase + (size_t)(eb + u) * TT));
#pragma unroll
            for (int u = 0; u < UNROLL; u++) {
                unsigned ored = __float_as_uint(v[u].x) | __float_as_uint(v[u].y) |
                                __float_as_uint(v[u].z) | __float_as_uint(v[u].w);
                if (ored) {  // rare
                    const int e = eb + u;
                    const float c[4] = {v[u].x, v[u].y, v[u].z, v[u].w};
#pragma unroll
                    for (int k = 0; k < 4; k++) {
                        if (__float_as_uint(c[k])) {
                            int idx = atomicAdd(&nhits, 1);
                            if (idx < HITS_MAX)
                                hits[idx] = (e << 8) | (tloc + k);
                        }
                    }
                }
            }
        }
    }
    __syncthreads();

    // ---- Phase B: warp w exclusively owns tt in [8w, 8w+8) ----
    {
        const int wid  = tid >> 5;          // 0..3
        const int lane = tid & 31;
        const int n = (nhits < HITS_MAX) ? nhits : HITS_MAX;
        for (int i = 0; i < n; i++) {
            const int h  = hits[i];         // LDS broadcast
            const int tt = h & 0xFF;
            if ((tt >> 3) == wid) {
                const int e = h >> 8;
                const float* col = g_featT + ((size_t)b * EE + e) * NF;
                // group values are exactly 1.0 at hits: accumulate feature col
                acc[tt][lane]      += col[lane];
                acc[tt][lane + 32] += col[lane + 32];
            }
        }
    }
    __syncthreads();

    // ---- writeout: out[b, f, t0+tt] = acc[tt][f] * inv_occ[tt] ----
    for (int i = tid; i < NF * TILE_T; i += NTHREADS) {
        const int f  = i / TILE_T;
        const int tt = i % TILE_T;          // consecutive tid -> consecutive t
        const int t  = t0 + tt;
        if (t < TT)
            out[((size_t)b * NF + f) * TT + t] = acc[tt][f] * inv_occ[tt];
    }
}

extern "C" void kernel_launch(void* const* d_in, const int* in_sizes, int n_in,
                              void* d_out, int out_size) {
    const float* features = (const float*)d_in[0];   // [B, NF, E]
    const float* group    = (const float*)d_in[1];   // [B, E, T]
    const float* occ      = (const float*)d_in[2];   // [B, T]
    float* out = (float*)d_out;                      // [B, NF, T]

    dim3 tgrid(EE / 32, NF / 32, BB);
    dim3 tblk(32, 8);
    transpose_feat_kernel<<<tgrid, tblk>>>(features);

    unpool_kernel<<<BB * NTILES, NTHREADS>>>(group, occ, out);
}

// round 4
// speedup vs baseline: 8.8854x; 1.0007x over previous
#include <cuda_runtime.h>

// MeshUnpool: out[b,f,t] = (1/occ[b,t]) * sum_e features[b,f,e] * group[b,e,t]
// group ~0.1%-dense 0/1 mask. Stream group once (384 MB), record sparse hits,
// accumulate via warp-exclusive tt ownership (no hot-path atomics).
//
// R4: fix grid starvation. R3 had 752 blocks = 5.08 blocks/SM of WORK, so
// residency capped at ~20 warps/SM regardless of launch_bounds. Now:
// TILE_T=16, 128 thr, NSPLIT=32 -> 1500 blocks = 40.5 warps/SM of work,
// 10 blocks/SM resident (reg-capped 51 -> UNROLL=5), 1.01 waves.

#define BB 4
#define NF 64
#define EE 4000
#define TT 6000

#define TILE_T 16
#define NLANE  (TILE_T / 4)        // 4 float4 lanes
#define NTHREADS 128
#define NSPLIT (NTHREADS / NLANE)  // 32 E-splits
#define EPT    (EE / NSPLIT)       // 125 rows per split
#define UNROLL 5                   // 25 iterations; 5 float4 fits 51-reg cap
#define NTILES ((TT + TILE_T - 1) / TILE_T)  // 375
#define HITS_MAX 512               // expected ~64 hits/block (Poisson)

// 4 MB scratch for transposed features [B][E][NF].
__device__ __align__(16) float g_featT[BB * EE * NF];

// ---------------------------------------------------------------------------
// Kernel 1: transpose features [B, NF, E] -> featT [B, E, NF]
// ---------------------------------------------------------------------------
__global__ void transpose_feat_kernel(const float* __restrict__ feat) {
    __shared__ float tile[32][33];
    const int b  = blockIdx.z;
    const int e0 = blockIdx.x * 32;
    const int f0 = blockIdx.y * 32;
    const int tx = threadIdx.x;   // 0..31
    const int ty = threadIdx.y;   // 0..7

#pragma unroll
    for (int j = 0; j < 32; j += 8)
        tile[ty + j][tx] = feat[((size_t)(b * NF + f0 + ty + j)) * EE + e0 + tx];
    __syncthreads();
#pragma unroll
    for (int j = 0; j < 32; j += 8)
        g_featT[((size_t)b * EE + (e0 + ty + j)) * NF + f0 + tx] = tile[tx][ty + j];
}

// ---------------------------------------------------------------------------
// Kernel 2: stream + two-phase sparse accumulate
// ---------------------------------------------------------------------------
__global__ void __launch_bounds__(NTHREADS, 10)
unpool_kernel(const float* __restrict__ group,
              const float* __restrict__ occ,
              float* __restrict__ out) {
    __shared__ float acc[TILE_T][NF + 1];   // bank(acc[tt][f]) = (tt+f)%32
    __shared__ float inv_occ[TILE_T];
    __shared__ int   hits[HITS_MAX];        // packed (e << 8) | tt
    __shared__ int   nhits;

    const int b    = blockIdx.x / NTILES;
    const int tile = blockIdx.x % NTILES;
    const int t0   = tile * TILE_T;
    const int tid  = threadIdx.x;

    // init
    for (int i = tid; i < TILE_T * (NF + 1); i += NTHREADS)
        (&acc[0][0])[i] = 0.0f;
    if (tid < TILE_T) {
        int t = t0 + tid;
        inv_occ[tid] = (t < TT) ? (1.0f / occ[(size_t)b * TT + t]) : 0.0f;
    }
    if (tid == 0) nhits = 0;
    __syncthreads();

    // ---- Phase A: stream group, record nonzero coordinates ----
    const int lane4  = tid & (NLANE - 1);   // which float4 inside the t-tile
    const int esplit = tid / NLANE;         // which E-split (0..31)
    const int tloc   = lane4 * 4;
    // t0+tloc < TT always (TT % TILE_T == 0)

    {
        const float* gbase = group + (size_t)b * EE * TT + t0 + tloc;
        const int e_begin = esplit * EPT;
        for (int it = 0; it < EPT / UNROLL; it++) {
            const int eb = e_begin + it * UNROLL;
            float4 v[UNROLL];
#pragma unroll
            for (int u = 0; u < UNROLL; u++)
                v[u] = __ldcs(reinterpret_cast<const float4*>(
                    gbase + (size_t)(eb + u) * TT));
            // batch skip: OR over all 20 words
            unsigned any = 0;
#pragma unroll
            for (int u = 0; u < UNROLL; u++)
                any |= __float_as_uint(v[u].x) | __float_as_uint(v[u].y) |
                       __float_as_uint(v[u].z) | __float_as_uint(v[u].w);
            if (any) {  // rare (~2% of thread-batches)
#pragma unroll
                for (int u = 0; u < UNROLL; u++) {
                    const float c[4] = {v[u].x, v[u].y, v[u].z, v[u].w};
#pragma unroll
                    for (int k = 0; k < 4; k++) {
                        if (__float_as_uint(c[k])) {
                            int idx = atomicAdd(&nhits, 1);
                            if (idx < HITS_MAX)
                                hits[idx] = ((eb + u) << 8) | (tloc + k);
                        }
                    }
                }
            }
        }
    }
    __syncthreads();

    // ---- Phase B: warp w exclusively owns tt in [4w, 4w+4) ----
    {
        const int wid  = tid >> 5;          // 0..3
        const int lane = tid & 31;
        const int n = (nhits < HITS_MAX) ? nhits : HITS_MAX;
        for (int i = 0; i < n; i++) {
            const int h  = hits[i];         // LDS broadcast
            const int tt = h & 0xFF;
            if ((tt >> 2) == wid) {
                const int e = h >> 8;
                const float* col = g_featT + ((size_t)b * EE + e) * NF;
                // group values at hits are exactly 1.0: accumulate feature col
                acc[tt][lane]      += col[lane];
                acc[tt][lane + 32] += col[lane + 32];
            }
        }
    }
    __syncthreads();

    // ---- writeout: out[b, f, t0+tt] = acc[tt][f] * inv_occ[tt] ----
    for (int i = tid; i < NF * TILE_T; i += NTHREADS) {
        const int f  = i / TILE_T;
        const int tt = i % TILE_T;
        out[((size_t)b * NF + f) * TT + t0 + tt] = acc[tt][f] * inv_occ[tt];
    }
}

extern "C" void kernel_launch(void* const* d_in, const int* in_sizes, int n_in,
                              void* d_out, int out_size) {
    const float* features = (const float*)d_in[0];   // [B, NF, E]
    const float* group    = (const float*)d_in[1];   // [B, E, T]
    const float* occ      = (const float*)d_in[2];   // [B, T]
    float* out = (float*)d_out;                      // [B, NF, T]

    dim3 tgrid(EE / 32, NF / 32, BB);
    dim3 tblk(32, 8);
    transpose_feat_kernel<<<tgrid, tblk>>>(features);

    unpool_kernel<<<BB * NTILES, NTHREADS>>>(group, occ, out);
}